// round 11
// baseline (speedup 1.0000x reference)
#include <cuda_runtime.h>
#include <cuda_bf16.h>
#include <float.h>

// BinsChamferLoss (R11: prep-once + full-occupancy float2-granularity main).
// sum over (b,p) of min_t | center(b,p) - target(b,t) |, targets masked to 0 below 0.001.
//
// k_prep (B blocks): sort centers, build LUT, publish to global.
// k_main (150 x B = 1200 blocks, 256 thr, 1 float2/thr -> 9600 warps ~= 65/SM):
// load centers+LUT, scatter targets into pred/succ slot words, flush, finisher.
//
// Slot word layout: w[i].lo = maxBelow enc for center i   (enc = bits(t)+1; 0 = none)
//                   w[i].hi = minAbove enc for center i-1 (enc = ~bits(t);  0 = none)

#define MAXB 32
#define P_BINS 256
#define MIN_DEPTH 0.001f
#define LUTN 1024
#define NW (P_BINS + 1)
#define TPB 256

__device__ float              g_centers[MAXB * P_BINS];
__device__ unsigned short     g_lut[MAXB * LUTN];
__device__ float              g_cmin[MAXB];
__device__ float              g_invw[MAXB];
__device__ unsigned long long g_W[MAXB * NW];   // zero-init = "none"
__device__ float              g_batchSum[MAXB];
__device__ unsigned int       g_cnt[MAXB];
__device__ unsigned int       g_done;

__device__ __forceinline__ unsigned int atom_add_acqrel(unsigned int* p, unsigned int v)
{
    unsigned int old;
    asm volatile("atom.acq_rel.gpu.global.add.u32 %0, [%1], %2;"
                 : "=r"(old) : "l"(p), "r"(v) : "memory");
    return old;
}

// ---------------- Kernel 1: sort centers + LUT, once per batch ------------
__global__ void __launch_bounds__(P_BINS)
k_prep(const float* __restrict__ bins)
{
    const int b   = blockIdx.x;
    const int tid = threadIdx.x;

    __shared__ float sC[P_BINS];

    float v;
    {
        const float* bb = bins + b * (P_BINS + 1);
        v = 0.5f * (bb[tid] + bb[tid + 1]);
    }

#pragma unroll
    for (int k = 2; k <= P_BINS; k <<= 1) {
#pragma unroll
        for (int j = k >> 1; j >= 1; j >>= 1) {
            bool up = ((tid & k) == 0);
            float other;
            if (j >= 32) {
                __syncthreads();
                sC[tid] = v;
                __syncthreads();
                other = sC[tid ^ j];
            } else {
                other = __shfl_xor_sync(0xffffffffu, v, j);
            }
            bool lower = ((tid & j) == 0);
            v = (lower == up) ? fminf(v, other) : fmaxf(v, other);
        }
    }
    __syncthreads();
    sC[tid] = v;
    g_centers[b * P_BINS + tid] = v;
    __syncthreads();

    const float cmin = sC[0];
    const float cmax = sC[P_BINS - 1];
    const float span = cmax - cmin;
    const float invw = (span > 0.0f) ? ((float)LUTN / span) : 0.0f;
    if (tid == 0) { g_cmin[b] = cmin; g_invw[b] = invw; }

    {
        float me = sC[tid];
        int st = min(LUTN, max(0, (int)((me - cmin) * invw)));
        int en;
        if (tid == P_BINS - 1) en = LUTN;
        else {
            float nx = sC[tid + 1];
            en = min(LUTN, max(0, (int)((nx - cmin) * invw)));
        }
        if (tid == 0) st = 0;
        for (int k = st; k < en; ++k) g_lut[b * LUTN + k] = (unsigned short)tid;
    }
}

// ---------------- Kernel 2: scatter + reduce (full occupancy) -------------
__global__ void __launch_bounds__(TPB, 8)
k_main(const float* __restrict__ depth, int M, int B, float* __restrict__ out)
{
    const int b    = blockIdx.y;
    const int tid  = threadIdx.x;
    const int lane = tid & 31;
    const int warp = tid >> 5;

    __shared__ float              sC[P_BINS];
    __shared__ unsigned long long sW[NW];
    __shared__ unsigned int       sLUT[LUTN / 2];
    __shared__ unsigned int       wA[8], wS[8];
    __shared__ float              wsum[8];
    __shared__ int                sFinisher;

    // ---- Prologue: coalesced loads of published tables ----
    sC[tid]         = g_centers[b * P_BINS + tid];
    sLUT[tid]       = ((const unsigned int*)(g_lut + b * LUTN))[tid];
    sLUT[tid + 256] = ((const unsigned int*)(g_lut + b * LUTN))[tid + 256];
    sW[tid]         = 0ull;
    if (tid == 0) sW[P_BINS] = 0ull;
    const float cmin = g_cmin[b];
    const float invw = g_invw[b];
    __syncthreads();

    const unsigned short* lut16 = (const unsigned short*)sLUT;

    // ---- Scatter: ONE float2 per thread (thin threads, 2x warps for hiding) ----
    {
        const float2* tgt2 = (const float2*)(depth + (long long)b * M);
        const int M2 = M >> 1;                     // M % 2 == 0
        const int i = blockIdx.x * TPB + tid;
        if (i < M2) {
            float2 vv = tgt2[i];
            float t[2] = {vv.x, vv.y};
            int   base[2];
            unsigned int tb[2];

            // Stage 1: mask + hint index + 2 independent LUT loads
#pragma unroll
            for (int q = 0; q < 2; ++q) {
                t[q] = (t[q] >= MIN_DEPTH) ? t[q] : 0.0f;
                tb[q] = __float_as_uint(t[q]);
                int k = min(LUTN - 1, max(0, (int)((t[q] - cmin) * invw)));
                base[q] = (int)lut16[k];
            }

            // Stage 2: walks + filter + atomics
#pragma unroll
            for (int q = 0; q < 2; ++q) {
                float tq = t[q];
                int bs = base[q];
                while (bs > 0 && sC[bs - 1] >= tq) --bs;
                float cur = 0.0f;
                while (bs < P_BINS) {
                    cur = sC[bs];
                    if (cur < tq) ++bs; else break;
                }
                // bs == lower_bound(sC, tq)

                unsigned long long w = sW[bs];       // one LDS.64 filter read
                unsigned int encA = tb[q] + 1u;
                if (bs < P_BINS && (unsigned int)w < encA)
                    atomicMax((unsigned int*)&sW[bs], encA);

                int ub = bs;
                if (bs < P_BINS && cur == tq) {      // ties ~never; exactness kept
                    ++ub;
                    while (ub < P_BINS && sC[ub] == tq) ++ub;
                }
                unsigned int encS = ~tb[q];
                if (ub > 0) {
                    unsigned int hi = (ub == bs) ? (unsigned int)(w >> 32)
                                                 : ((unsigned int*)&sW[ub])[1];
                    if (hi < encS)
                        atomicMax(((unsigned int*)&sW[ub]) + 1, encS);
                }
            }
        }
    }
    __syncthreads();

    // ---- Flush to global scratch (filtered; monotone-safe) ----
    {
#pragma unroll
        for (int rep = 0; rep < 2; ++rep) {
            int idx = (rep == 0) ? tid : P_BINS;
            if (rep == 1 && tid != 0) break;
            unsigned long long vv = sW[idx];
            if (vv) {
                unsigned long long* gw = &g_W[b * NW + idx];
                unsigned long long g = *gw;
                unsigned int lo = (unsigned int)vv, hi = (unsigned int)(vv >> 32);
                unsigned int* p = (unsigned int*)gw;
                if (lo > (unsigned int)g)         atomicMax(p, lo);
                if (hi > (unsigned int)(g >> 32)) atomicMax(p + 1, hi);
            }
        }
    }

    // ---- Last block of this batch reduces it (acq_rel arrive) ----
    if (tid == 0) {
        unsigned int old = atom_add_acqrel(&g_cnt[b], 1u);
        sFinisher = (old == (unsigned)(gridDim.x - 1));
    }
    __syncthreads();
    if (!sFinisher) return;

    unsigned long long w0 = g_W[b * NW + tid];
    unsigned long long w1 = g_W[b * NW + tid + 1];
    __syncthreads();                               // reads before resets
    g_W[b * NW + tid] = 0ull;                      // reset for graph replay
    if (tid == 0) { g_W[b * NW + P_BINS] = 0ull; g_cnt[b] = 0u; }

    unsigned int encA = (unsigned int)w0;          // A[tid]
    unsigned int encS = (unsigned int)(w1 >> 32);  // S[tid]

    // prefix-max / suffix-max scans, shuffle-based
    unsigned int pv = encA;
#pragma unroll
    for (int o = 1; o < 32; o <<= 1) {
        unsigned int n = __shfl_up_sync(0xffffffffu, pv, o);
        if (lane >= o) pv = max(pv, n);
    }
    if (lane == 31) wA[warp] = pv;

    unsigned int sv = encS;
#pragma unroll
    for (int o = 1; o < 32; o <<= 1) {
        unsigned int n = __shfl_down_sync(0xffffffffu, sv, o);
        if (lane + o < 32) sv = max(sv, n);
    }
    if (lane == 0) wS[warp] = sv;
    __syncthreads();

    unsigned int offA = 0u, offS = 0u;
    for (int w = 0; w < warp; ++w)     offA = max(offA, wA[w]);
    for (int w = warp + 1; w < 8; ++w) offS = max(offS, wS[w]);
    pv = max(pv, offA);
    sv = max(sv, offS);

    float c   = sC[tid];
    float dLo = pv ? (c - __uint_as_float(pv - 1u)) : FLT_MAX;
    float dHi = sv ? (__uint_as_float(~sv) - c)     : FLT_MAX;
    float d   = fminf(dLo, dHi);

#pragma unroll
    for (int o = 16; o >= 1; o >>= 1) d += __shfl_down_sync(0xffffffffu, d, o);
    if (lane == 0) wsum[warp] = d;
    __syncthreads();

    if (tid == 0) {
        float s = 0.0f;
        for (int w = 0; w < 8; ++w) s += wsum[w];
        g_batchSum[b] = s;

        unsigned int old = atom_add_acqrel(&g_done, 1u);
        if (old == (unsigned)(B - 1)) {
            float tot = 0.0f;
            for (int i = 0; i < B; ++i) tot += g_batchSum[i];
            out[0] = tot;
            g_done = 0u;   // reset for next replay
        }
    }
}

extern "C" void kernel_launch(void* const* d_in, const int* in_sizes, int n_in,
                              void* d_out, int out_size)
{
    int bi = 0, di = 1;
    if (n_in >= 2 && in_sizes[0] > in_sizes[1]) { bi = 1; di = 0; }
    const float* bins  = (const float*)d_in[bi];
    const float* depth = (const float*)d_in[di];

    const int B = in_sizes[bi] / (P_BINS + 1);
    const int M = in_sizes[di] / B;

    const int M2 = M >> 1;
    const int splits = (M2 + TPB - 1) / TPB;   // 150 for 320x240: one float2/thread

    k_prep<<<B, P_BINS>>>(bins);
    dim3 grid(splits, B);
    k_main<<<grid, TPB>>>(depth, M, B, (float*)d_out);
}